// round 4
// baseline (speedup 1.0000x reference)
#include <cuda_runtime.h>
#include <cstdint>

// Problem constants (match reference init_kwargs)
static constexpr int H = 1080;
static constexpr int W = 1920;
static constexpr int NPIX = H * W;           // 2,073,600 = 8100 * 256
static constexpr float ZNEAR = 0.2f;
static constexpr float SH_C0 = 0.28209479177387814f;

// Scratch z-buffer holding COMPLEMENTED keys, resolved by atomicMax.
//   stored = ~((depth_bits << 32) | idx), miss sentinel = 0.
// Zero-initialized at module load; resolve_kernel writes 0 back after
// consuming each slot, so the buffer is all-zero at the start of every call
// (no separate init pass needed).
__device__ unsigned long long g_zbuf[NPIX];

// ---------------------------------------------------------------------------
// Pass 1: project all points, atomicMax(~(depth, idx)) into pixel buckets.
// Explicit round-to-nearest intrinsics (no FMA fusion) => bit-exact with the
// reference's per-op float32 evaluation (off-diagonal terms are exactly 0).
// Two points per thread; means3D loaded as three float2 (24B-aligned pairs).
// ---------------------------------------------------------------------------
__global__ void project_kernel(const float* __restrict__ means3D,
                               const float* __restrict__ viewmatrix,
                               const float* __restrict__ projmatrix,
                               int n) {
    int t = blockIdx.x * blockDim.x + threadIdx.x;
    int i0 = 2 * t;
    if (i0 >= n) return;

    // Load up to 2 points (6 floats) with vector loads.
    const float2* __restrict__ m2 =
        reinterpret_cast<const float2*>(means3D + 6 * (size_t)t);
    float2 a = __ldg(&m2[0]);
    float2 b = (i0 + 1 < n) ? __ldg(&m2[1]) : make_float2(0.f, 0.f);
    float2 c = (i0 + 1 < n) ? __ldg(&m2[2]) : make_float2(0.f, 1.f);

    float P00 = __ldg(&projmatrix[0]),  P10 = __ldg(&projmatrix[4]);
    float P20 = __ldg(&projmatrix[8]),  P30 = __ldg(&projmatrix[12]);
    float P01 = __ldg(&projmatrix[1]),  P11 = __ldg(&projmatrix[5]);
    float P21 = __ldg(&projmatrix[9]),  P31 = __ldg(&projmatrix[13]);
    float P03 = __ldg(&projmatrix[3]),  P13 = __ldg(&projmatrix[7]);
    float P23 = __ldg(&projmatrix[11]), P33 = __ldg(&projmatrix[15]);
    float V02 = __ldg(&viewmatrix[2]),  V12 = __ldg(&viewmatrix[6]);
    float V22 = __ldg(&viewmatrix[10]), V32 = __ldg(&viewmatrix[14]);

    #pragma unroll
    for (int k = 0; k < 2; k++) {
        int i = i0 + k;
        if (i >= n) break;
        float x, y, z;
        if (k == 0) { x = a.x; y = a.y; z = b.x; }
        else        { x = b.y; y = c.x; z = c.y; }

        float phx = __fadd_rn(__fadd_rn(__fmul_rn(x, P00), __fmul_rn(y, P10)),
                              __fadd_rn(__fmul_rn(z, P20), P30));
        float phy = __fadd_rn(__fadd_rn(__fmul_rn(x, P01), __fmul_rn(y, P11)),
                              __fadd_rn(__fmul_rn(z, P21), P31));
        float phw = __fadd_rn(__fadd_rn(__fmul_rn(x, P03), __fmul_rn(y, P13)),
                              __fadd_rn(__fmul_rn(z, P23), P33));

        float inv_w = __fdiv_rn(1.0f, __fadd_rn(phw, 1e-7f));

        float depth = __fadd_rn(__fadd_rn(__fmul_rn(x, V02), __fmul_rn(y, V12)),
                                __fadd_rn(__fmul_rn(z, V22), V32));

        float ndcx = __fmul_rn(phx, inv_w);
        float ndcy = __fmul_rn(phy, inv_w);
        float fx = __fsub_rn(__fmul_rn(__fmul_rn(__fadd_rn(ndcx, 1.0f),
                                                 (float)W), 0.5f), 0.5f);
        float fy = __fsub_rn(__fmul_rn(__fmul_rn(__fadd_rn(ndcy, 1.0f),
                                                 (float)H), 0.5f), 0.5f);

        if (!(depth > ZNEAR)) continue;
        if (!(fx > -2.0f && fx < (float)(W + 1) &&
              fy > -2.0f && fy < (float)(H + 1))) continue;
        int px = (int)rintf(fx);
        int py = (int)rintf(fy);
        if (px < 0 || px >= W || py < 0 || py >= H) continue;

        unsigned long long key =
            ((unsigned long long)__float_as_uint(depth) << 32) | (unsigned)i;
        atomicMax(&g_zbuf[py * W + px], ~key);
    }
}

// ---------------------------------------------------------------------------
// Pass 2: resolve. One block = 256 consecutive pixels (NPIX = 8100*256).
// Reads + resets zbuf, writes all outputs fully coalesced.
// out layout (floats): idx[NPIX] | col[NPIX*3] | depth[NPIX] | feat[NPIX*32]
// ---------------------------------------------------------------------------
__global__ __launch_bounds__(256) void resolve_kernel(
        const float* __restrict__ shs,        // stride 48 floats
        const float* __restrict__ feat,       // stride 32 floats
        const float* __restrict__ bg,
        float* __restrict__ out, int n) {
    __shared__ unsigned s_idx[256];

    int t = threadIdx.x;
    int p0 = blockIdx.x * 256;
    int p = p0 + t;

    float* __restrict__ o_idx  = out;
    float* __restrict__ o_col  = out + (size_t)NPIX;
    float* __restrict__ o_dep  = out + (size_t)4 * NPIX;
    float* __restrict__ o_feat = out + (size_t)5 * NPIX;

    unsigned long long stored = g_zbuf[p];
    g_zbuf[p] = 0ULL;                       // reset for the next call
    unsigned long long key = ~stored;       // valid iff stored != 0
    unsigned idx = (unsigned)(key & 0xFFFFFFFFull);
    bool hit = (stored != 0ULL) && (idx < (unsigned)n);
    s_idx[t] = hit ? idx : 0xFFFFFFFFu;

    o_idx[p] = hit ? (float)idx : -1.0f;
    o_dep[p] = hit ? __uint_as_float((unsigned)(key >> 32)) : 0.0f;

    __syncthreads();

    // Color: 3 rounds of 256 contiguous floats. j = channel-major flat index.
    #pragma unroll
    for (int r = 0; r < 3; r++) {
        int j = r * 256 + t;          // 0..767
        int pix = j / 3;
        int ch = j - pix * 3;
        unsigned id2 = s_idx[pix];
        float v;
        if (id2 != 0xFFFFFFFFu) {
            v = fmaxf(__fadd_rn(__fmul_rn(SH_C0,
                        __ldg(&shs[(size_t)id2 * 48 + ch])), 0.5f), 0.0f);
        } else {
            v = __ldg(&bg[ch]);
        }
        o_col[(size_t)p0 * 3 + j] = v;
    }

    // Features: 8 rounds; 8 threads per pixel, one float4 chunk each.
    int pix_in_round = t >> 3;        // 0..31
    int chunk = t & 7;                // 0..7
    #pragma unroll
    for (int r = 0; r < 8; r++) {
        int pix = r * 32 + pix_in_round;      // 0..255
        unsigned id2 = s_idx[pix];
        float4 v;
        if (id2 != 0xFFFFFFFFu) {
            v = __ldg(&reinterpret_cast<const float4*>(
                        feat + (size_t)id2 * 32)[chunk]);
        } else {
            v = make_float4(0.f, 0.f, 0.f, 0.f);
        }
        reinterpret_cast<float4*>(o_feat + ((size_t)p0 + pix) * 32)[chunk] = v;
    }
}

// ---------------------------------------------------------------------------
// Launch. Input order (metadata): means3D, normal, means2D, feature_vector,
// shs, scales, rotations, viewmatrix, projmatrix, bg, campos
// ---------------------------------------------------------------------------
extern "C" void kernel_launch(void* const* d_in, const int* in_sizes, int n_in,
                              void* d_out, int out_size) {
    const float* means3D    = (const float*)d_in[0];
    const float* feat       = (const float*)d_in[3];
    const float* shs        = (const float*)d_in[4];
    const float* viewmatrix = (const float*)d_in[7];
    const float* projmatrix = (const float*)d_in[8];
    const float* bg         = (const float*)d_in[9];

    int n = in_sizes[0] / 3;

    {
        int threads = 256;
        int pairs = (n + 1) / 2;
        int blocks = (pairs + threads - 1) / threads;
        project_kernel<<<blocks, threads>>>(means3D, viewmatrix, projmatrix, n);
    }
    {
        int threads = 256;
        int blocks = NPIX / 256;                  // 8100, exact
        resolve_kernel<<<blocks, threads>>>(shs, feat, bg, (float*)d_out, n);
    }
}

// round 5
// speedup vs baseline: 1.9070x; 1.9070x over previous
#include <cuda_runtime.h>
#include <cstdint>

// Problem constants (match reference init_kwargs)
static constexpr int H = 1080;
static constexpr int W = 1920;
static constexpr int NPIX = H * W;           // 2,073,600 = 8100 * 256
static constexpr float ZNEAR = 0.2f;
static constexpr float SH_C0 = 0.28209479177387814f;

// Scratch z-buffer holding COMPLEMENTED keys, resolved by atomicMax.
//   stored = ~((depth_bits << 32) | idx), miss sentinel = 0.
// Cleared to zero each call via cudaMemsetAsync (a graph-capturable memset
// node) before the projection pass. Resolve reads it read-only.
__device__ unsigned long long g_zbuf[NPIX];

// ---------------------------------------------------------------------------
// Pass 1: project all points, atomicMax(~(depth, idx)) into pixel buckets.
// Explicit round-to-nearest intrinsics (no FMA fusion) => bit-exact with the
// reference's per-op float32 evaluation (off-diagonal terms are exactly 0).
// Two points per thread; means3D loaded as three float2 (24B-aligned pairs).
// ---------------------------------------------------------------------------
__global__ void project_kernel(const float* __restrict__ means3D,
                               const float* __restrict__ viewmatrix,
                               const float* __restrict__ projmatrix,
                               int n) {
    int t = blockIdx.x * blockDim.x + threadIdx.x;
    int i0 = 2 * t;
    if (i0 >= n) return;

    const float2* __restrict__ m2 =
        reinterpret_cast<const float2*>(means3D + 6 * (size_t)t);
    float2 a = __ldg(&m2[0]);
    float2 b = (i0 + 1 < n) ? __ldg(&m2[1]) : make_float2(0.f, 0.f);
    float2 c = (i0 + 1 < n) ? __ldg(&m2[2]) : make_float2(0.f, 1.f);

    float P00 = __ldg(&projmatrix[0]),  P10 = __ldg(&projmatrix[4]);
    float P20 = __ldg(&projmatrix[8]),  P30 = __ldg(&projmatrix[12]);
    float P01 = __ldg(&projmatrix[1]),  P11 = __ldg(&projmatrix[5]);
    float P21 = __ldg(&projmatrix[9]),  P31 = __ldg(&projmatrix[13]);
    float P03 = __ldg(&projmatrix[3]),  P13 = __ldg(&projmatrix[7]);
    float P23 = __ldg(&projmatrix[11]), P33 = __ldg(&projmatrix[15]);
    float V02 = __ldg(&viewmatrix[2]),  V12 = __ldg(&viewmatrix[6]);
    float V22 = __ldg(&viewmatrix[10]), V32 = __ldg(&viewmatrix[14]);

    #pragma unroll
    for (int k = 0; k < 2; k++) {
        int i = i0 + k;
        if (i >= n) break;
        float x, y, z;
        if (k == 0) { x = a.x; y = a.y; z = b.x; }
        else        { x = b.y; y = c.x; z = c.y; }

        float phx = __fadd_rn(__fadd_rn(__fmul_rn(x, P00), __fmul_rn(y, P10)),
                              __fadd_rn(__fmul_rn(z, P20), P30));
        float phy = __fadd_rn(__fadd_rn(__fmul_rn(x, P01), __fmul_rn(y, P11)),
                              __fadd_rn(__fmul_rn(z, P21), P31));
        float phw = __fadd_rn(__fadd_rn(__fmul_rn(x, P03), __fmul_rn(y, P13)),
                              __fadd_rn(__fmul_rn(z, P23), P33));

        float inv_w = __fdiv_rn(1.0f, __fadd_rn(phw, 1e-7f));

        float depth = __fadd_rn(__fadd_rn(__fmul_rn(x, V02), __fmul_rn(y, V12)),
                                __fadd_rn(__fmul_rn(z, V22), V32));

        float ndcx = __fmul_rn(phx, inv_w);
        float ndcy = __fmul_rn(phy, inv_w);
        float fx = __fsub_rn(__fmul_rn(__fmul_rn(__fadd_rn(ndcx, 1.0f),
                                                 (float)W), 0.5f), 0.5f);
        float fy = __fsub_rn(__fmul_rn(__fmul_rn(__fadd_rn(ndcy, 1.0f),
                                                 (float)H), 0.5f), 0.5f);

        if (!(depth > ZNEAR)) continue;
        if (!(fx > -2.0f && fx < (float)(W + 1) &&
              fy > -2.0f && fy < (float)(H + 1))) continue;
        int px = (int)rintf(fx);
        int py = (int)rintf(fy);
        if (px < 0 || px >= W || py < 0 || py >= H) continue;

        unsigned long long key =
            ((unsigned long long)__float_as_uint(depth) << 32) | (unsigned)i;
        atomicMax(&g_zbuf[py * W + px], ~key);
    }
}

// ---------------------------------------------------------------------------
// Pass 2: resolve. One block = 256 consecutive pixels (NPIX = 8100*256).
// zbuf is READ-ONLY here; all output stores fully coalesced.
// out layout (floats): idx[NPIX] | col[NPIX*3] | depth[NPIX] | feat[NPIX*32]
// ---------------------------------------------------------------------------
__global__ __launch_bounds__(256) void resolve_kernel(
        const float* __restrict__ shs,        // stride 48 floats
        const float* __restrict__ feat,       // stride 32 floats
        const float* __restrict__ bg,
        float* __restrict__ out, int n) {
    __shared__ unsigned s_idx[256];

    int t = threadIdx.x;
    int p0 = blockIdx.x * 256;
    int p = p0 + t;

    float* __restrict__ o_idx  = out;
    float* __restrict__ o_col  = out + (size_t)NPIX;
    float* __restrict__ o_dep  = out + (size_t)4 * NPIX;
    float* __restrict__ o_feat = out + (size_t)5 * NPIX;

    unsigned long long stored = __ldg(&g_zbuf[p]);
    unsigned long long key = ~stored;       // valid iff stored != 0
    unsigned idx = (unsigned)(key & 0xFFFFFFFFull);
    bool hit = (stored != 0ULL) && (idx < (unsigned)n);
    s_idx[t] = hit ? idx : 0xFFFFFFFFu;

    o_idx[p] = hit ? (float)idx : -1.0f;
    o_dep[p] = hit ? __uint_as_float((unsigned)(key >> 32)) : 0.0f;

    __syncthreads();

    // Color: 3 rounds of 256 contiguous floats. j = channel-major flat index.
    #pragma unroll
    for (int r = 0; r < 3; r++) {
        int j = r * 256 + t;          // 0..767
        int pix = j / 3;
        int ch = j - pix * 3;
        unsigned id2 = s_idx[pix];
        float v;
        if (id2 != 0xFFFFFFFFu) {
            v = fmaxf(__fadd_rn(__fmul_rn(SH_C0,
                        __ldg(&shs[(size_t)id2 * 48 + ch])), 0.5f), 0.0f);
        } else {
            v = __ldg(&bg[ch]);
        }
        o_col[(size_t)p0 * 3 + j] = v;
    }

    // Features: 8 rounds; 8 threads per pixel, one float4 chunk each.
    int pix_in_round = t >> 3;        // 0..31
    int chunk = t & 7;                // 0..7
    #pragma unroll
    for (int r = 0; r < 8; r++) {
        int pix = r * 32 + pix_in_round;      // 0..255
        unsigned id2 = s_idx[pix];
        float4 v;
        if (id2 != 0xFFFFFFFFu) {
            v = __ldg(&reinterpret_cast<const float4*>(
                        feat + (size_t)id2 * 32)[chunk]);
        } else {
            v = make_float4(0.f, 0.f, 0.f, 0.f);
        }
        reinterpret_cast<float4*>(o_feat + ((size_t)p0 + pix) * 32)[chunk] = v;
    }
}

// ---------------------------------------------------------------------------
// Launch. Input order (metadata): means3D, normal, means2D, feature_vector,
// shs, scales, rotations, viewmatrix, projmatrix, bg, campos
// ---------------------------------------------------------------------------
extern "C" void kernel_launch(void* const* d_in, const int* in_sizes, int n_in,
                              void* d_out, int out_size) {
    const float* means3D    = (const float*)d_in[0];
    const float* feat       = (const float*)d_in[3];
    const float* shs        = (const float*)d_in[4];
    const float* viewmatrix = (const float*)d_in[7];
    const float* projmatrix = (const float*)d_in[8];
    const float* bg         = (const float*)d_in[9];

    int n = in_sizes[0] / 3;

    // Clear the z-buffer with a memset node (graph-capturable, full fill BW).
    void* zbuf_ptr = nullptr;
    cudaGetSymbolAddress(&zbuf_ptr, g_zbuf);
    cudaMemsetAsync(zbuf_ptr, 0, (size_t)NPIX * sizeof(unsigned long long), 0);

    {
        int threads = 256;
        int pairs = (n + 1) / 2;
        int blocks = (pairs + threads - 1) / threads;
        project_kernel<<<blocks, threads>>>(means3D, viewmatrix, projmatrix, n);
    }
    {
        int threads = 256;
        int blocks = NPIX / 256;                  // 8100, exact
        resolve_kernel<<<blocks, threads>>>(shs, feat, bg, (float*)d_out, n);
    }
}